// round 7
// baseline (speedup 1.0000x reference)
#include <cuda_runtime.h>

#define N_NODES 50000
#define N_EDGES 800000
#define T_DIM   8
#define NF_IN   32
#define NH1     40
#define NH2     64
#define NF_OUT  64
#define SCAN_NB ((N_NODES + 1023) / 1024)   // 49

// Scratch (device globals; allocation-free per harness rules)
__device__ __align__(16) float g_bufA[N_NODES * T_DIM * 64];
__device__ __align__(16) float g_bufB[N_NODES * T_DIM * 64];
__device__ float g_onorm[N_NODES];
__device__ float g_inorm[N_NODES];
__device__ int   g_odeg [N_NODES];
__device__ int   g_indeg[N_NODES];
__device__ int   g_offsets[N_NODES + 1];
__device__ int   g_cursor [N_NODES];
__device__ int   g_bsum [SCAN_NB];
__device__ int   g_esrc [N_EDGES];
__device__ __align__(16) float g_WcT[3 * 64 * 64];   // [k][i][o]

static inline int cdiv(int a, int b) { return (a + b - 1) / b; }

// ---------------------------------------------------------------------------
// Launch 0: zero degree counters + COALESCED transpose tf [N,32,8] -> bufA [N,8,32]
// (round-3 form — proven innocent of the rel_err bug, which was scan2)
__global__ void k_prep(const float* __restrict__ tf) {
    __shared__ float sh[8][32 * 9];     // per-warp node tile, padded [f][t]
    int gid = blockIdx.x * blockDim.x + threadIdx.x;
    if (gid < N_NODES) { g_odeg[gid] = 0; g_indeg[gid] = 0; }

    int w = threadIdx.x >> 5, lane = threadIdx.x & 31;
    int node = blockIdx.x * 8 + w;                      // 50000 = 6250*8 exact
    const float4* src4 = reinterpret_cast<const float4*>(tf + (size_t)node * 256);
    #pragma unroll
    for (int h = 0; h < 2; ++h) {
        float4 v = __ldg(&src4[h * 32 + lane]);
        int l = (h * 32 + lane) * 4;                    // linear [f][t] index
        int f = l >> 3, t = l & 7;                      // 4 consecutive t
        float* p = &sh[w][f * 9 + t];
        p[0] = v.x; p[1] = v.y; p[2] = v.z; p[3] = v.w;
    }
    __syncwarp();
    float* outp = g_bufA + (size_t)node * 256;
    #pragma unroll
    for (int j = 0; j < 8; ++j)                         // out[t=j][f=lane]
        outp[j * 32 + lane] = sh[w][lane * 9 + j];
}

// Launch 1: integer degree histogram
__global__ void k_deg(const int* __restrict__ src, const int* __restrict__ dst) {
    int i = blockIdx.x * blockDim.x + threadIdx.x;
    if (i < N_EDGES) {
        atomicAdd(&g_odeg[src[i]], 1);
        atomicAdd(&g_indeg[dst[i]], 1);
    }
}

// Launch 2: per-block exclusive scan (shuffle-based), block totals to g_bsum
__global__ void k_scan1() {
    __shared__ int wsum[32];
    int lane = threadIdx.x & 31, wid = threadIdx.x >> 5;
    int idx = blockIdx.x * 1024 + threadIdx.x;
    int v = (idx < N_NODES) ? g_indeg[idx] : 0;
    int x = v;
    #pragma unroll
    for (int o = 1; o < 32; o <<= 1) {
        int y = __shfl_up_sync(0xffffffffu, x, o);
        if (lane >= o) x += y;
    }
    if (lane == 31) wsum[wid] = x;
    __syncthreads();
    if (wid == 0) {
        int s = wsum[lane];
        #pragma unroll
        for (int o = 1; o < 32; o <<= 1) {
            int y = __shfl_up_sync(0xffffffffu, s, o);
            if (lane >= o) s += y;
        }
        wsum[lane] = s;
    }
    __syncthreads();
    int base = (wid > 0) ? wsum[wid - 1] : 0;
    int incl = base + x;
    if (idx < N_NODES) g_offsets[idx] = incl - v;       // block-local exclusive
    if (threadIdx.x == 1023) g_bsum[blockIdx.x] = incl; // block total
}

// Launch 3: scan the 49 block sums (1 warp). All shuffles convergent.
__global__ void k_scan2() {
    int lane = threadIdx.x;
    int v0 = (lane < SCAN_NB) ? g_bsum[lane] : 0;
    int v1 = (lane + 32 < SCAN_NB) ? g_bsum[lane + 32] : 0;
    int x0 = v0, x1 = v1;
    #pragma unroll
    for (int o = 1; o < 32; o <<= 1) {
        int y0 = __shfl_up_sync(0xffffffffu, x0, o);
        int y1 = __shfl_up_sync(0xffffffffu, x1, o);
        if (lane >= o) { x0 += y0; x1 += y1; }
    }
    int tot0 = __shfl_sync(0xffffffffu, x0, 31);   // convergent
    int tot1 = __shfl_sync(0xffffffffu, x1, 31);   // convergent
    if (lane < SCAN_NB) g_bsum[lane] = x0 - v0;
    if (lane + 32 < SCAN_NB) g_bsum[lane + 32] = tot0 + x1 - v1;
    if (lane == 0) g_offsets[N_NODES] = tot0 + tot1;
}

// Launch 4: fixup offsets + cursor + norms + conv-weight transpose
__global__ void k_scan3(const float* __restrict__ Wc) {
    int i = blockIdx.x * blockDim.x + threadIdx.x;
    if (i < N_NODES) {
        int off = g_offsets[i] + g_bsum[i >> 10];
        g_offsets[i] = off;
        g_cursor[i]  = off;
        g_onorm[i] = rsqrtf(fmaxf((float)g_odeg[i], 1.0f));
        g_inorm[i] = rsqrtf(fmaxf((float)g_indeg[i], 1.0f));
    } else {
        int j = i - N_NODES;
        if (j < 3 * 64 * 64) {
            int k = j / 4096, rem = j % 4096;
            int ii = rem / 64, o = rem % 64;
            g_WcT[j] = Wc[(o * 64 + ii) * 3 + k];
        }
    }
}

// Launch 5: fill CSR edge-source list (dst-bucketed)
__global__ void k_fill(const int* __restrict__ src, const int* __restrict__ dst) {
    int i = blockIdx.x * blockDim.x + threadIdx.x;
    if (i < N_EDGES) {
        int pos = atomicAdd(&g_cursor[dst[i]], 1);
        g_esrc[pos] = src[i];
    }
}

// ---------------------------------------------------------------------------
// Pull body (proven): accumulate over edge range [beg, end).
template<int LC, int NCH, bool SRCSCALE>
__device__ __forceinline__ void pull_range(const float* __restrict__ hin,
                                           int beg, int end, int lane, float4* acc) {
    #pragma unroll
    for (int j = 0; j < NCH; ++j) acc[j] = make_float4(0.f, 0.f, 0.f, 0.f);

    int e = beg;
    for (; e + 2 <= end; e += 2) {
        int s0 = __ldg(&g_esrc[e]);
        int s1 = __ldg(&g_esrc[e + 1]);
        float c0 = SRCSCALE ? __ldg(&g_onorm[s0]) : 1.0f;
        float c1 = SRCSCALE ? __ldg(&g_onorm[s1]) : 1.0f;
        const float4* h0 = reinterpret_cast<const float4*>(hin) + (size_t)s0 * LC;
        const float4* h1 = reinterpret_cast<const float4*>(hin) + (size_t)s1 * LC;
        #pragma unroll
        for (int j = 0; j < NCH; ++j) {
            int c = lane + j * 32;
            if (c < LC) {
                float4 a = __ldg(&h0[c]);
                float4 b = __ldg(&h1[c]);
                if (SRCSCALE) {
                    acc[j].x += a.x * c0 + b.x * c1;
                    acc[j].y += a.y * c0 + b.y * c1;
                    acc[j].z += a.z * c0 + b.z * c1;
                    acc[j].w += a.w * c0 + b.w * c1;
                } else {
                    acc[j].x += a.x + b.x;
                    acc[j].y += a.y + b.y;
                    acc[j].z += a.z + b.z;
                    acc[j].w += a.w + b.w;
                }
            }
        }
    }
    if (e < end) {
        int s0 = __ldg(&g_esrc[e]);
        float c0 = SRCSCALE ? __ldg(&g_onorm[s0]) : 1.0f;
        const float4* h0 = reinterpret_cast<const float4*>(hin) + (size_t)s0 * LC;
        #pragma unroll
        for (int j = 0; j < NCH; ++j) {
            int c = lane + j * 32;
            if (c < LC) {
                float4 a = __ldg(&h0[c]);
                if (SRCSCALE) {
                    acc[j].x += a.x * c0; acc[j].y += a.y * c0;
                    acc[j].z += a.z * c0; acc[j].w += a.w * c0;
                } else {
                    acc[j].x += a.x; acc[j].y += a.y;
                    acc[j].z += a.z; acc[j].w += a.w;
                }
            }
        }
    }
}

// Fused pull + matmul, 2 warps per node (edge-range split), 4 nodes per block.
// yout[n,t,:] = act((inorm[n] * agg[n,t,:]) @ W + b) * (OSCALE ? onorm[n] : 1)
template<int FIN, int FOUT, bool SRCSCALE, bool RELU, bool OSCALE>
__global__ __launch_bounds__(256)
void k_pullmm(const float* __restrict__ hin, const float* __restrict__ W,
              const float* __restrict__ b, float* __restrict__ yout) {
    constexpr int LC  = T_DIM * FIN / 4;   // float4 chunks per node tile
    constexpr int NCH = (LC + 31) / 32;
    constexpr int QF  = FIN / 4;
    constexpr int RS4 = QF + 1;            // padded row stride (float4)
    constexpr int RSF = FIN + 4;
    constexpr int OG  = FOUT / 4;
    constexpr int HP  = (T_DIM * OG) / 2;  // outputs per warp-half
    __shared__ float xsh[4][T_DIM * RSF];
    __shared__ float psh[4][LC * 4];       // warp-1 partial sums

    int warp = threadIdx.x >> 5, lane = threadIdx.x & 31;
    int slot = warp >> 1, half = warp & 1;
    int node = blockIdx.x * 4 + slot;      // 50000 = 12500*4 exact

    int beg = __ldg(&g_offsets[node]);
    int end = __ldg(&g_offsets[node + 1]);
    int mid = beg + ((end - beg) >> 1);

    float4 acc[NCH];
    pull_range<LC, NCH, SRCSCALE>(hin, half ? mid : beg, half ? end : mid, lane, acc);

    // warp 1 stores partials; warp 0 combines, scales, stages tile
    if (half) {
        float4* ps4 = reinterpret_cast<float4*>(psh[slot]);
        #pragma unroll
        for (int j = 0; j < NCH; ++j) {
            int c = lane + j * 32;
            if (c < LC) ps4[c] = acc[j];
        }
    }
    __syncthreads();
    if (!half) {
        float inrm = __ldg(&g_inorm[node]);
        float4* xs4 = reinterpret_cast<float4*>(xsh[slot]);
        const float4* ps4 = reinterpret_cast<const float4*>(psh[slot]);
        #pragma unroll
        for (int j = 0; j < NCH; ++j) {
            int c = lane + j * 32;
            if (c < LC) {
                int t = c / QF, fq = c % QF;
                float4 p = ps4[c];
                float4 v = acc[j];
                v.x = (v.x + p.x) * inrm; v.y = (v.y + p.y) * inrm;
                v.z = (v.z + p.z) * inrm; v.w = (v.w + p.w) * inrm;
                xs4[t * RS4 + fq] = v;
            }
        }
    }
    __syncthreads();

    // matmul: both warps, each handles HP output positions
    const float4* W4 = reinterpret_cast<const float4*>(W);
    float onrm = OSCALE ? __ldg(&g_onorm[node]) : 1.0f;
    for (int p = half * HP + lane; p < (half + 1) * HP; p += 32) {
        int t = p / OG, og = p % OG;
        float4 o = reinterpret_cast<const float4*>(b)[og];
        const float* xr = &xsh[slot][t * RSF];
        #pragma unroll 8
        for (int i = 0; i < FIN; ++i) {
            float xv = xr[i];
            float4 w = __ldg(&W4[i * OG + og]);
            o.x = fmaf(xv, w.x, o.x);
            o.y = fmaf(xv, w.y, o.y);
            o.z = fmaf(xv, w.z, o.z);
            o.w = fmaf(xv, w.w, o.w);
        }
        if (RELU) {
            o.x = fmaxf(o.x, 0.0f); o.y = fmaxf(o.y, 0.0f);
            o.z = fmaxf(o.z, 0.0f); o.w = fmaxf(o.w, 0.0f);
        }
        if (OSCALE) { o.x *= onrm; o.y *= onrm; o.z *= onrm; o.w *= onrm; }
        reinterpret_cast<float4*>(yout + (size_t)node * (T_DIM * FOUT) + t * FOUT)[og] = o;
    }
}

// Fused layer 3: pull + matmul (64->64) + conv1d(k=3,pad=1), 2 warps per node.
__global__ __launch_bounds__(256)
void k_pullmm3_conv(const float* __restrict__ hin, const float* __restrict__ W,
                    const float* __restrict__ b, const float* __restrict__ bc,
                    float* __restrict__ out) {
    constexpr int FIN = 64, LC = 128, NCH = 4, QF = 16, RS4 = 17, RSF = 68;
    __shared__ float xsh[4][576];            // input tile [t][f] pad / conv out [o][t] pad-9
    __shared__ float ysh[4][T_DIM * RSF];    // matmul output, padded rows
    __shared__ float psh[4][512];            // warp-1 pull partials

    int warp = threadIdx.x >> 5, lane = threadIdx.x & 31;
    int slot = warp >> 1, half = warp & 1;
    int node = blockIdx.x * 4 + slot;

    int beg = __ldg(&g_offsets[node]);
    int end = __ldg(&g_offsets[node + 1]);
    int mid = beg + ((end - beg) >> 1);

    float4 acc[NCH];
    pull_range<LC, NCH, false>(hin, half ? mid : beg, half ? end : mid, lane, acc);

    if (half) {
        float4* ps4 = reinterpret_cast<float4*>(psh[slot]);
        #pragma unroll
        for (int j = 0; j < NCH; ++j) ps4[lane + j * 32] = acc[j];
    }
    __syncthreads();
    if (!half) {
        float inrm = __ldg(&g_inorm[node]);
        float4* xs4 = reinterpret_cast<float4*>(xsh[slot]);
        const float4* ps4 = reinterpret_cast<const float4*>(psh[slot]);
        #pragma unroll
        for (int j = 0; j < NCH; ++j) {
            int c = lane + j * 32;
            int t = c / QF, fq = c % QF;
            float4 p = ps4[c];
            float4 v = acc[j];
            v.x = (v.x + p.x) * inrm; v.y = (v.y + p.y) * inrm;
            v.z = (v.z + p.z) * inrm; v.w = (v.w + p.w) * inrm;
            xs4[t * RS4 + fq] = v;
        }
    }
    __syncthreads();

    // matmul 64->64 into ysh (both warps, 64 positions each)
    const float4* W4 = reinterpret_cast<const float4*>(W);
    float4* ys4 = reinterpret_cast<float4*>(ysh[slot]);
    for (int p = half * 64 + lane; p < (half + 1) * 64; p += 32) {
        int t = p >> 4, og = p & 15;
        float4 o = reinterpret_cast<const float4*>(b)[og];
        const float* xr = &xsh[slot][t * RSF];
        #pragma unroll 8
        for (int i = 0; i < FIN; ++i) {
            float xv = xr[i];
            float4 w = __ldg(&W4[i * 16 + og]);
            o.x = fmaf(xv, w.x, o.x);
            o.y = fmaf(xv, w.y, o.y);
            o.z = fmaf(xv, w.z, o.z);
            o.w = fmaf(xv, w.w, o.w);
        }
        ys4[t * RS4 + og] = o;
    }
    __syncthreads();   // xsh consumed, ysh complete

    // conv over t (k=3, pad=1); output staged into osh = xsh reuse, [o][t] stride 9
    float* osh = xsh[slot];
    const float4* Wt4 = reinterpret_cast<const float4*>(g_WcT);
    for (int p = half * 64 + lane; p < (half + 1) * 64; p += 32) {
        int t = p >> 4, og = p & 15;
        float4 o = reinterpret_cast<const float4*>(bc)[og];
        #pragma unroll
        for (int k = 0; k < 3; ++k) {
            int tr = t + k - 1;
            if (tr < 0 || tr >= T_DIM) continue;
            const float* xr = &ysh[slot][tr * RSF];
            #pragma unroll 8
            for (int i = 0; i < 64; ++i) {
                float xv = xr[i];
                float4 w = __ldg(&Wt4[(k * 64 + i) * 16 + og]);
                o.x = fmaf(xv, w.x, o.x);
                o.y = fmaf(xv, w.y, o.y);
                o.z = fmaf(xv, w.z, o.z);
                o.w = fmaf(xv, w.w, o.w);
            }
        }
        int o0 = og * 4;
        osh[(o0 + 0) * 9 + t] = o.x;
        osh[(o0 + 1) * 9 + t] = o.y;
        osh[(o0 + 2) * 9 + t] = o.z;
        osh[(o0 + 3) * 9 + t] = o.w;
    }
    __syncthreads();

    // coalesced output copy: 64 lanes (2 warps) over 512 floats
    float* ob = out + (size_t)node * 512;
    int wl = half * 32 + lane;
    #pragma unroll
    for (int k = 0; k < 8; ++k) {
        int j = wl + k * 64;
        ob[j] = osh[(j >> 3) * 9 + (j & 7)];
    }
}

// ---------------------------------------------------------------------------
extern "C" void kernel_launch(void* const* d_in, const int* in_sizes, int n_in,
                              void* d_out, int out_size) {
    const float* tf  = (const float*)d_in[0];
    const int*   src = (const int*)  d_in[1];
    const int*   dst = (const int*)  d_in[2];
    const float* W1  = (const float*)d_in[3];
    const float* b1  = (const float*)d_in[4];
    const float* W2  = (const float*)d_in[5];
    const float* b2  = (const float*)d_in[6];
    const float* W3  = (const float*)d_in[7];
    const float* b3  = (const float*)d_in[8];
    const float* Wc  = (const float*)d_in[9];
    const float* bc  = (const float*)d_in[10];
    float* out = (float*)d_out;

    float *bufA, *bufB;
    cudaGetSymbolAddress((void**)&bufA, g_bufA);
    cudaGetSymbolAddress((void**)&bufB, g_bufB);

    const int TB = 256;

    // CSR build + prologue
    k_prep <<<N_NODES / 8, TB>>>(tf);
    k_deg  <<<cdiv(N_EDGES, TB), TB>>>(src, dst);
    k_scan1<<<SCAN_NB, 1024>>>();
    k_scan2<<<1, 32>>>();
    k_scan3<<<cdiv(N_NODES + 3 * 64 * 64, TB), TB>>>(Wc);
    k_fill <<<cdiv(N_EDGES, TB), TB>>>(src, dst);

    // ---- layer 1: pull + (32 -> 40) relu, onorm pre-applied for layer 2 ----
    k_pullmm<32, 40, true, true, true><<<N_NODES / 4, TB>>>(bufA, W1, b1, bufB);

    // ---- layer 2: pull + (40 -> 64) relu, onorm pre-applied for layer 3 ----
    k_pullmm<40, 64, false, true, true><<<N_NODES / 4, TB>>>(bufB, W2, b2, bufA);

    // ---- layer 3: pull + (64 -> 64) + conv1d fused -> out [N, 64, 8] ----
    k_pullmm3_conv<<<N_NODES / 4, TB>>>(bufA, W3, b3, bc, out);
}

// round 8
// speedup vs baseline: 1.0386x; 1.0386x over previous
#include <cuda_runtime.h>

#define N_NODES 50000
#define N_EDGES 800000
#define T_DIM   8
#define NF_IN   32
#define NH1     40
#define NH2     64
#define NF_OUT  64

// Scratch (device globals; allocation-free per harness rules)
__device__ __align__(16) float g_bufA[N_NODES * T_DIM * 64];
__device__ __align__(16) float g_bufB[N_NODES * T_DIM * 64];
__device__ float g_onorm[N_NODES];
__device__ float g_inorm[N_NODES];
__device__ int   g_odeg [N_NODES];   // zero on entry (static init + self-restore)
__device__ int   g_indeg[N_NODES];   // zero on entry (static init + self-restore)
__device__ int   g_offsets[N_NODES + 1];
__device__ int   g_cursor [N_NODES];
__device__ int   g_esrc [N_EDGES];
__device__ __align__(16) float g_WcT[3 * 64 * 64];   // [k][i][o]

static inline int cdiv(int a, int b) { return (a + b - 1) / b; }

// ---------------------------------------------------------------------------
// Launch 0: integer degree histogram (counters are zero on entry: zero-init
// at load, re-zeroed by the final kernel of every call -> invariant holds)
__global__ void k_deg(const int* __restrict__ src, const int* __restrict__ dst) {
    int i = blockIdx.x * blockDim.x + threadIdx.x;
    if (i < N_EDGES) {
        atomicAdd(&g_odeg[src[i]], 1);
        atomicAdd(&g_indeg[dst[i]], 1);
    }
}

// Launch 1: single-block fused CSR prologue.
// WcT transpose, then exclusive scan of indeg -> offsets/cursor + norms.
__global__ void k_scanall(const float* __restrict__ Wc) {
    __shared__ int wsum[32];
    __shared__ int s_carry;
    int lane = threadIdx.x & 31, wid = threadIdx.x >> 5;

    // conv-weight transpose Wc [o,i,k] -> WcT [k,i,o] (independent work)
    for (int j = threadIdx.x; j < 3 * 64 * 64; j += 1024) {
        int k = j / 4096, rem = j % 4096;
        int ii = rem / 64, o = rem % 64;
        g_WcT[j] = Wc[(o * 64 + ii) * 3 + k];
    }

    if (threadIdx.x == 0) s_carry = 0;
    __syncthreads();

    for (int base = 0; base < N_NODES; base += 1024) {
        int idx = base + threadIdx.x;
        int v = (idx < N_NODES) ? g_indeg[idx] : 0;
        int x = v;
        #pragma unroll
        for (int o = 1; o < 32; o <<= 1) {
            int y = __shfl_up_sync(0xffffffffu, x, o);
            if (lane >= o) x += y;
        }
        if (lane == 31) wsum[wid] = x;
        __syncthreads();
        if (wid == 0) {
            int s = wsum[lane];
            #pragma unroll
            for (int o = 1; o < 32; o <<= 1) {
                int y = __shfl_up_sync(0xffffffffu, s, o);
                if (lane >= o) s += y;
            }
            wsum[lane] = s;
        }
        __syncthreads();
        int carry = s_carry;
        int wbase = (wid > 0) ? wsum[wid - 1] : 0;
        int excl = carry + wbase + x - v;
        if (idx < N_NODES) {
            g_offsets[idx] = excl;
            g_cursor[idx]  = excl;
            g_onorm[idx] = rsqrtf(fmaxf((float)g_odeg[idx], 1.0f));
            g_inorm[idx] = rsqrtf(fmaxf((float)v, 1.0f));
        }
        __syncthreads();
        if (threadIdx.x == 1023) s_carry = carry + wbase + x;
        __syncthreads();
    }
    if (threadIdx.x == 0) g_offsets[N_NODES] = s_carry;
}

// Launch 2: fill CSR edge-source list (dst-bucketed)
__global__ void k_fill(const int* __restrict__ src, const int* __restrict__ dst) {
    int i = blockIdx.x * blockDim.x + threadIdx.x;
    if (i < N_EDGES) {
        int pos = atomicAdd(&g_cursor[dst[i]], 1);
        g_esrc[pos] = src[i];
    }
}

// ---------------------------------------------------------------------------
// Pull body (proven round-5/6 code): warp accumulates node w's feature tile.
template<int LC, int NCH, bool SRCSCALE>
__device__ __forceinline__ void pull_node(const float* __restrict__ hin,
                                          int w, int lane, float4* acc) {
    int beg = __ldg(&g_offsets[w]);
    int end = __ldg(&g_offsets[w + 1]);
    #pragma unroll
    for (int j = 0; j < NCH; ++j) acc[j] = make_float4(0.f, 0.f, 0.f, 0.f);

    int e = beg;
    for (; e + 2 <= end; e += 2) {
        int s0 = __ldg(&g_esrc[e]);
        int s1 = __ldg(&g_esrc[e + 1]);
        float c0 = SRCSCALE ? __ldg(&g_onorm[s0]) : 1.0f;
        float c1 = SRCSCALE ? __ldg(&g_onorm[s1]) : 1.0f;
        const float4* h0 = reinterpret_cast<const float4*>(hin) + (size_t)s0 * LC;
        const float4* h1 = reinterpret_cast<const float4*>(hin) + (size_t)s1 * LC;
        #pragma unroll
        for (int j = 0; j < NCH; ++j) {
            int c = lane + j * 32;
            if (c < LC) {
                float4 a = __ldg(&h0[c]);
                float4 b = __ldg(&h1[c]);
                if (SRCSCALE) {
                    acc[j].x += a.x * c0 + b.x * c1;
                    acc[j].y += a.y * c0 + b.y * c1;
                    acc[j].z += a.z * c0 + b.z * c1;
                    acc[j].w += a.w * c0 + b.w * c1;
                } else {
                    acc[j].x += a.x + b.x;
                    acc[j].y += a.y + b.y;
                    acc[j].z += a.z + b.z;
                    acc[j].w += a.w + b.w;
                }
            }
        }
    }
    if (e < end) {
        int s0 = __ldg(&g_esrc[e]);
        float c0 = SRCSCALE ? __ldg(&g_onorm[s0]) : 1.0f;
        const float4* h0 = reinterpret_cast<const float4*>(hin) + (size_t)s0 * LC;
        #pragma unroll
        for (int j = 0; j < NCH; ++j) {
            int c = lane + j * 32;
            if (c < LC) {
                float4 a = __ldg(&h0[c]);
                if (SRCSCALE) {
                    acc[j].x += a.x * c0; acc[j].y += a.y * c0;
                    acc[j].z += a.z * c0; acc[j].w += a.w * c0;
                } else {
                    acc[j].x += a.x; acc[j].y += a.y;
                    acc[j].z += a.z; acc[j].w += a.w;
                }
            }
        }
    }
}

// Shared matmul epilogue: warp computes y[t,:] = act(x @ W + b) * scale
template<int FIN, int FOUT, bool RELU, bool OSCALE>
__device__ __forceinline__ void mm_epilogue(const float* __restrict__ xrow, int rsf,
                                            const float* __restrict__ W,
                                            const float* __restrict__ b,
                                            float onrm, int lane, int node,
                                            float* __restrict__ yout) {
    constexpr int OG = FOUT / 4;
    const float4* W4 = reinterpret_cast<const float4*>(W);
    for (int p = lane; p < T_DIM * OG; p += 32) {
        int t = p / OG, og = p % OG;
        float4 o = reinterpret_cast<const float4*>(b)[og];
        const float* xr = xrow + t * rsf;
        #pragma unroll 8
        for (int i = 0; i < FIN; ++i) {
            float xv = xr[i];
            float4 w = __ldg(&W4[i * OG + og]);
            o.x = fmaf(xv, w.x, o.x);
            o.y = fmaf(xv, w.y, o.y);
            o.z = fmaf(xv, w.z, o.z);
            o.w = fmaf(xv, w.w, o.w);
        }
        if (RELU) {
            o.x = fmaxf(o.x, 0.0f); o.y = fmaxf(o.y, 0.0f);
            o.z = fmaxf(o.z, 0.0f); o.w = fmaxf(o.w, 0.0f);
        }
        if (OSCALE) { o.x *= onrm; o.y *= onrm; o.z *= onrm; o.w *= onrm; }
        reinterpret_cast<float4*>(yout + (size_t)node * (T_DIM * FOUT) + t * FOUT)[og] = o;
    }
}

// Launch 3 (PROFILED): layer 1 fused pull(+transpose) + matmul 32->40 relu.
// Gathers directly from tf [N, 32, 8] (contiguous 256-float rows); the
// [f][t] -> [t][f] transpose is folded into the smem staging index map.
__global__ __launch_bounds__(256)
void k_pullmm1(const float* __restrict__ tf, const float* __restrict__ W,
               const float* __restrict__ b, float* __restrict__ yout) {
    constexpr int LC = 64, NCH = 2;        // 256 floats per tf row
    constexpr int RSF = NF_IN + 4;         // padded [t][f] row stride = 36
    __shared__ float xsh[8][T_DIM * RSF];

    int warp = threadIdx.x >> 5, lane = threadIdx.x & 31;
    int node = blockIdx.x * 8 + warp;      // 50000 = 6250*8 exact

    float4 acc[NCH];
    pull_node<LC, NCH, true>(tf, node, lane, acc);   // chunks in [f][t] order

    float inrm = __ldg(&g_inorm[node]);
    #pragma unroll
    for (int j = 0; j < NCH; ++j) {
        int c = lane + j * 32;             // c = f*2 + (t/4)
        int f = c >> 1, t0 = (c & 1) * 4;
        float4 v = acc[j];
        xsh[warp][(t0 + 0) * RSF + f] = v.x * inrm;
        xsh[warp][(t0 + 1) * RSF + f] = v.y * inrm;
        xsh[warp][(t0 + 2) * RSF + f] = v.z * inrm;
        xsh[warp][(t0 + 3) * RSF + f] = v.w * inrm;
    }
    __syncwarp();

    float onrm = __ldg(&g_onorm[node]);
    mm_epilogue<NF_IN, NH1, true, true>(xsh[warp], RSF, W, b, onrm, lane, node, yout);
}

// Launch 4: layer 2 fused pull + matmul 40->64 relu (round-6 proven structure)
__global__ __launch_bounds__(256)
void k_pullmm2(const float* __restrict__ hin, const float* __restrict__ W,
               const float* __restrict__ b, float* __restrict__ yout) {
    constexpr int FIN = 40, LC = 80, NCH = 3, QF = 10, RS4 = 11, RSF = 44;
    __shared__ float xsh[8][T_DIM * RSF];

    int warp = threadIdx.x >> 5, lane = threadIdx.x & 31;
    int node = blockIdx.x * 8 + warp;

    float4 acc[NCH];
    pull_node<LC, NCH, false>(hin, node, lane, acc);

    float inrm = __ldg(&g_inorm[node]);
    float4* xs4 = reinterpret_cast<float4*>(xsh[warp]);
    #pragma unroll
    for (int j = 0; j < NCH; ++j) {
        int c = lane + j * 32;
        if (c < LC) {
            int t = c / QF, fq = c % QF;
            float4 v = acc[j];
            v.x *= inrm; v.y *= inrm; v.z *= inrm; v.w *= inrm;
            xs4[t * RS4 + fq] = v;
        }
    }
    __syncwarp();

    float onrm = __ldg(&g_onorm[node]);
    mm_epilogue<FIN, NH2, true, true>(xsh[warp], RSF, W, b, onrm, lane, node, yout);
}

// Launch 5: layer 3 fused pull + matmul 64->64 + conv1d(k=3,pad=1) -> out.
// Also self-restores the degree counters to zero for the next call.
__global__ __launch_bounds__(256)
void k_pullmm3_conv(const float* __restrict__ hin, const float* __restrict__ W,
                    const float* __restrict__ b, const float* __restrict__ bc,
                    float* __restrict__ out) {
    constexpr int FIN = 64, LC = 128, NCH = 4, QF = 16, RS4 = 17, RSF = 68;
    __shared__ float xsh[8][576];            // [t][f] padded / reused as [o][t] pad-9
    __shared__ float ysh[8][T_DIM * RSF];

    // self-restore: counters dead after k_scanall; zero for next launch call
    int gid = blockIdx.x * blockDim.x + threadIdx.x;
    if (gid < N_NODES) { g_odeg[gid] = 0; g_indeg[gid] = 0; }

    int warp = threadIdx.x >> 5, lane = threadIdx.x & 31;
    int node = blockIdx.x * 8 + warp;

    float4 acc[NCH];
    pull_node<LC, NCH, false>(hin, node, lane, acc);

    float inrm = __ldg(&g_inorm[node]);
    float4* xs4 = reinterpret_cast<float4*>(xsh[warp]);
    #pragma unroll
    for (int j = 0; j < NCH; ++j) {
        int c = lane + j * 32;
        int t = c / QF, fq = c % QF;
        float4 v = acc[j];
        v.x *= inrm; v.y *= inrm; v.z *= inrm; v.w *= inrm;
        xs4[t * RS4 + fq] = v;
    }
    __syncwarp();

    // matmul 64 -> 64 into ysh
    const float4* W4 = reinterpret_cast<const float4*>(W);
    float4* ys4 = reinterpret_cast<float4*>(ysh[warp]);
    #pragma unroll
    for (int p = lane; p < T_DIM * 16; p += 32) {
        int t = p >> 4, og = p & 15;
        float4 o = reinterpret_cast<const float4*>(b)[og];
        const float* xr = &xsh[warp][t * RSF];
        #pragma unroll 8
        for (int i = 0; i < FIN; ++i) {
            float xv = xr[i];
            float4 w = __ldg(&W4[i * 16 + og]);
            o.x = fmaf(xv, w.x, o.x);
            o.y = fmaf(xv, w.y, o.y);
            o.z = fmaf(xv, w.z, o.z);
            o.w = fmaf(xv, w.w, o.w);
        }
        ys4[t * RS4 + og] = o;
    }
    __syncwarp();   // xsh consumed, ysh complete

    // conv over t (k=3, pad=1); output staged into osh = xsh reuse, [o][t] stride 9
    float* osh = xsh[warp];
    const float4* Wt4 = reinterpret_cast<const float4*>(g_WcT);
    #pragma unroll
    for (int p = lane; p < T_DIM * 16; p += 32) {
        int t = p >> 4, og = p & 15;
        float4 o = reinterpret_cast<const float4*>(bc)[og];
        #pragma unroll
        for (int k = 0; k < 3; ++k) {
            int tr = t + k - 1;
            if (tr < 0 || tr >= T_DIM) continue;
            const float* xr = &ysh[warp][tr * RSF];
            #pragma unroll 8
            for (int i = 0; i < 64; ++i) {
                float xv = xr[i];
                float4 w = __ldg(&Wt4[(k * 64 + i) * 16 + og]);
                o.x = fmaf(xv, w.x, o.x);
                o.y = fmaf(xv, w.y, o.y);
                o.z = fmaf(xv, w.z, o.z);
                o.w = fmaf(xv, w.w, o.w);
            }
        }
        int o0 = og * 4;
        osh[(o0 + 0) * 9 + t] = o.x;
        osh[(o0 + 1) * 9 + t] = o.y;
        osh[(o0 + 2) * 9 + t] = o.z;
        osh[(o0 + 3) * 9 + t] = o.w;
    }
    __syncwarp();

    float* ob = out + (size_t)node * 512;
    #pragma unroll
    for (int k = 0; k < 16; ++k) {
        int j = lane + k * 32;
        ob[j] = osh[(j >> 3) * 9 + (j & 7)];
    }
}

// ---------------------------------------------------------------------------
extern "C" void kernel_launch(void* const* d_in, const int* in_sizes, int n_in,
                              void* d_out, int out_size) {
    const float* tf  = (const float*)d_in[0];
    const int*   src = (const int*)  d_in[1];
    const int*   dst = (const int*)  d_in[2];
    const float* W1  = (const float*)d_in[3];
    const float* b1  = (const float*)d_in[4];
    const float* W2  = (const float*)d_in[5];
    const float* b2  = (const float*)d_in[6];
    const float* W3  = (const float*)d_in[7];
    const float* b3  = (const float*)d_in[8];
    const float* Wc  = (const float*)d_in[9];
    const float* bc  = (const float*)d_in[10];
    float* out = (float*)d_out;

    float *bufA, *bufB;
    cudaGetSymbolAddress((void**)&bufA, g_bufA);
    cudaGetSymbolAddress((void**)&bufB, g_bufB);

    const int TB = 256;

    k_deg    <<<cdiv(N_EDGES, TB), TB>>>(src, dst);      // 0
    k_scanall<<<1, 1024>>>(Wc);                          // 1
    k_fill   <<<cdiv(N_EDGES, TB), TB>>>(src, dst);      // 2

    // 3 (PROFILED): layer 1 pull directly from tf (+folded transpose) + mm
    k_pullmm1<<<N_NODES / 8, TB>>>(tf, W1, b1, bufB);
    // 4: layer 2
    k_pullmm2<<<N_NODES / 8, TB>>>(bufB, W2, b2, bufA);
    // 5: layer 3 + conv (+ counter self-restore)
    k_pullmm3_conv<<<N_NODES / 8, TB>>>(bufA, W3, b3, bc, out);
}

// round 10
// speedup vs baseline: 2.0605x; 1.9840x over previous
#include <cuda_runtime.h>
#include <cuda_fp16.h>
#include <cstdint>

#define N_NODES 50000
#define N_EDGES 800000
#define T_DIM   8
#define NF_IN   32
#define NH1     40
#define NH2     64
#define NF_OUT  64

// Scratch (device globals; allocation-free per harness rules)
__device__ __align__(16) __half g_thf  [N_NODES * 256];   // tf transposed [n][t][32], fp16
__device__ __align__(16) __half g_hbufB[N_NODES * 320];   // layer1 out [n][t][40], fp16
__device__ __align__(16) __half g_hbufA[N_NODES * 512];   // layer2 out [n][t][64], fp16
__device__ float g_onorm[N_NODES];
__device__ float g_inorm[N_NODES];
__device__ int   g_odeg [N_NODES];   // zero on entry (static init + self-restore)
__device__ int   g_indeg[N_NODES];   // zero on entry (static init + self-restore)
__device__ int   g_offsets[N_NODES + 1];
__device__ int   g_cursor [N_NODES];
__device__ int   g_esrc [N_EDGES];
__device__ __align__(16) float g_WcT[3 * 64 * 64];        // [k][i][o]

static inline int cdiv(int a, int b) { return (a + b - 1) / b; }

__device__ __forceinline__ unsigned int pack_half2(float a, float b) {
    __half2 h = __floats2half2_rn(a, b);
    return *reinterpret_cast<unsigned int*>(&h);
}

// ---------------------------------------------------------------------------
// Launch 0: degree histogram (blocks 0..3124) + tf transpose->fp16 (all blocks)
__global__ void k_degprep(const float* __restrict__ tf,
                          const int* __restrict__ src, const int* __restrict__ dst) {
    __shared__ float sh[8][32 * 9];     // per-warp node tile, padded [f][t]
    int gid = blockIdx.x * blockDim.x + threadIdx.x;
    if (gid < N_EDGES) {                // 3125*256 = 800000 exactly
        atomicAdd(&g_odeg[src[gid]], 1);
        atomicAdd(&g_indeg[dst[gid]], 1);
    }

    int w = threadIdx.x >> 5, lane = threadIdx.x & 31;
    int node = blockIdx.x * 8 + w;      // 6250*8 = 50000 exactly
    const float4* src4 = reinterpret_cast<const float4*>(tf + (size_t)node * 256);
    #pragma unroll
    for (int h = 0; h < 2; ++h) {
        float4 v = __ldg(&src4[h * 32 + lane]);
        int l = (h * 32 + lane) * 4;    // linear [f][t] index
        int f = l >> 3, t = l & 7;
        float* p = &sh[w][f * 9 + t];
        p[0] = v.x; p[1] = v.y; p[2] = v.z; p[3] = v.w;
    }
    __syncwarp();
    // write [t][f] as half: lane -> t = lane>>2, f0 = (lane&3)*8 (8 features)
    int t = lane >> 2, f0 = (lane & 3) * 8;
    float v[8];
    #pragma unroll
    for (int m = 0; m < 8; ++m) v[m] = sh[w][(f0 + m) * 9 + t];
    uint4 u;
    u.x = pack_half2(v[0], v[1]); u.y = pack_half2(v[2], v[3]);
    u.z = pack_half2(v[4], v[5]); u.w = pack_half2(v[6], v[7]);
    *reinterpret_cast<uint4*>(g_thf + (size_t)node * 256 + t * 32 + f0) = u;
}

// Launch 1: single-block fused CSR prologue (proven round-8 code)
__global__ void k_scanall(const float* __restrict__ Wc) {
    __shared__ int wsum[32];
    __shared__ int s_carry;
    int lane = threadIdx.x & 31, wid = threadIdx.x >> 5;

    for (int j = threadIdx.x; j < 3 * 64 * 64; j += 1024) {
        int k = j / 4096, rem = j % 4096;
        int ii = rem / 64, o = rem % 64;
        g_WcT[j] = Wc[(o * 64 + ii) * 3 + k];
    }
    if (threadIdx.x == 0) s_carry = 0;
    __syncthreads();

    for (int base = 0; base < N_NODES; base += 1024) {
        int idx = base + threadIdx.x;
        int v = (idx < N_NODES) ? g_indeg[idx] : 0;
        int x = v;
        #pragma unroll
        for (int o = 1; o < 32; o <<= 1) {
            int y = __shfl_up_sync(0xffffffffu, x, o);
            if (lane >= o) x += y;
        }
        if (lane == 31) wsum[wid] = x;
        __syncthreads();
        if (wid == 0) {
            int s = wsum[lane];
            #pragma unroll
            for (int o = 1; o < 32; o <<= 1) {
                int y = __shfl_up_sync(0xffffffffu, s, o);
                if (lane >= o) s += y;
            }
            wsum[lane] = s;
        }
        __syncthreads();
        int carry = s_carry;
        int wbase = (wid > 0) ? wsum[wid - 1] : 0;
        int excl = carry + wbase + x - v;
        if (idx < N_NODES) {
            g_offsets[idx] = excl;
            g_cursor[idx]  = excl;
            g_onorm[idx] = rsqrtf(fmaxf((float)g_odeg[idx], 1.0f));
            g_inorm[idx] = rsqrtf(fmaxf((float)v, 1.0f));
        }
        __syncthreads();
        if (threadIdx.x == 1023) s_carry = carry + wbase + x;
        __syncthreads();
    }
    if (threadIdx.x == 0) g_offsets[N_NODES] = s_carry;
}

// Launch 2: fill CSR edge-source list (dst-bucketed)
__global__ void k_fill(const int* __restrict__ src, const int* __restrict__ dst) {
    int i = blockIdx.x * blockDim.x + threadIdx.x;
    if (i < N_EDGES) {
        int pos = atomicAdd(&g_cursor[dst[i]], 1);
        g_esrc[pos] = src[i];
    }
}

// ---------------------------------------------------------------------------
// fp16 pull: accumulate 8 halves (one 16B chunk) into fp32 acc
template<bool SC>
__device__ __forceinline__ void acc8(const uint4 u, float s, float* a) {
    float2 f0 = __half22float2(*reinterpret_cast<const __half2*>(&u.x));
    float2 f1 = __half22float2(*reinterpret_cast<const __half2*>(&u.y));
    float2 f2 = __half22float2(*reinterpret_cast<const __half2*>(&u.z));
    float2 f3 = __half22float2(*reinterpret_cast<const __half2*>(&u.w));
    if (SC) {
        a[0] = fmaf(f0.x, s, a[0]); a[1] = fmaf(f0.y, s, a[1]);
        a[2] = fmaf(f1.x, s, a[2]); a[3] = fmaf(f1.y, s, a[3]);
        a[4] = fmaf(f2.x, s, a[4]); a[5] = fmaf(f2.y, s, a[5]);
        a[6] = fmaf(f3.x, s, a[6]); a[7] = fmaf(f3.y, s, a[7]);
    } else {
        a[0] += f0.x; a[1] += f0.y; a[2] += f1.x; a[3] += f1.y;
        a[4] += f2.x; a[5] += f2.y; a[6] += f3.x; a[7] += f3.y;
    }
}

// Pull (proven structure, fp16 rows): LC = number of 16B chunks per node row.
template<int LC, int NCH, bool SRCSCALE>
__device__ __forceinline__ void pull_node_h(const __half* __restrict__ hin,
                                            int w, int lane, float acc[][8]) {
    int beg = __ldg(&g_offsets[w]);
    int end = __ldg(&g_offsets[w + 1]);
    #pragma unroll
    for (int j = 0; j < NCH; ++j)
        #pragma unroll
        for (int m = 0; m < 8; ++m) acc[j][m] = 0.0f;

    int e = beg;
    for (; e + 2 <= end; e += 2) {
        int s0 = __ldg(&g_esrc[e]);
        int s1 = __ldg(&g_esrc[e + 1]);
        float c0 = SRCSCALE ? __ldg(&g_onorm[s0]) : 1.0f;
        float c1 = SRCSCALE ? __ldg(&g_onorm[s1]) : 1.0f;
        const uint4* h0 = reinterpret_cast<const uint4*>(hin + (size_t)s0 * (LC * 8));
        const uint4* h1 = reinterpret_cast<const uint4*>(hin + (size_t)s1 * (LC * 8));
        #pragma unroll
        for (int j = 0; j < NCH; ++j) {
            int c = lane + j * 32;
            if (c < LC) {
                uint4 a = __ldg(&h0[c]);
                uint4 b = __ldg(&h1[c]);
                acc8<SRCSCALE>(a, c0, acc[j]);
                acc8<SRCSCALE>(b, c1, acc[j]);
            }
        }
    }
    if (e < end) {
        int s0 = __ldg(&g_esrc[e]);
        float c0 = SRCSCALE ? __ldg(&g_onorm[s0]) : 1.0f;
        const uint4* h0 = reinterpret_cast<const uint4*>(hin + (size_t)s0 * (LC * 8));
        #pragma unroll
        for (int j = 0; j < NCH; ++j) {
            int c = lane + j * 32;
            if (c < LC) {
                uint4 a = __ldg(&h0[c]);
                acc8<SRCSCALE>(a, c0, acc[j]);
            }
        }
    }
}

// Stage fp32 tile into padded smem: chunk c -> t = (c*8)/FIN, f0 = (c*8)%FIN
template<int LC, int NCH, int FIN, int RSF>
__device__ __forceinline__ void stage_tile(float* __restrict__ xrow, int lane,
                                           float acc[][8], float inrm) {
    constexpr int CPT = FIN / 8;   // chunks per t-row
    #pragma unroll
    for (int j = 0; j < NCH; ++j) {
        int c = lane + j * 32;
        if (c < LC) {
            int t = c / CPT, f0 = (c % CPT) * 8;
            float* p = xrow + t * RSF + f0;
            float4 v0 = make_float4(acc[j][0] * inrm, acc[j][1] * inrm,
                                    acc[j][2] * inrm, acc[j][3] * inrm);
            float4 v1 = make_float4(acc[j][4] * inrm, acc[j][5] * inrm,
                                    acc[j][6] * inrm, acc[j][7] * inrm);
            *reinterpret_cast<float4*>(p)     = v0;
            *reinterpret_cast<float4*>(p + 4) = v1;
        }
    }
}

// ---------------------------------------------------------------------------
// Launch 3 (PROFILED): layer 1 = pull(tf fp16) + matmul 32->40 relu -> fp16
__global__ __launch_bounds__(256)
void k_pullmm1(const float* __restrict__ W, const float* __restrict__ b,
               uint2* __restrict__ yout) {
    constexpr int LC = 32, NCH = 1, FIN = 32, RSF = 36, OG = 10;
    __shared__ float xsh[8][T_DIM * RSF];

    int warp = threadIdx.x >> 5, lane = threadIdx.x & 31;
    int node = blockIdx.x * 8 + warp;

    float acc[NCH][8];
    pull_node_h<LC, NCH, true>(g_thf, node, lane, acc);
    stage_tile<LC, NCH, FIN, RSF>(xsh[warp], lane, acc, __ldg(&g_inorm[node]));
    __syncwarp();

    // epilogue: lane -> og = lane%10, g = lane/10 (3 t-rows each; lanes 30,31 idle)
    if (lane < 30) {
        int og = lane % OG, g = lane / OG;
        float onrm = __ldg(&g_onorm[node]);
        const float4* W4 = reinterpret_cast<const float4*>(W);
        float4 a0 = reinterpret_cast<const float4*>(b)[og];
        float4 a1 = a0, a2 = a0;
        const float* x0 = &xsh[warp][(g * 3 + 0) * RSF];
        const float* x1 = &xsh[warp][(g * 3 + 1) * RSF];
        const float* x2 = &xsh[warp][(g * 3 + 2) * RSF];   // t=8 slot unused if g==2
        bool has2 = (g * 3 + 2) < T_DIM;
        #pragma unroll 8
        for (int i = 0; i < FIN; ++i) {
            float4 w = __ldg(&W4[i * OG + og]);
            float v0 = x0[i], v1 = x1[i];
            a0.x = fmaf(v0, w.x, a0.x); a0.y = fmaf(v0, w.y, a0.y);
            a0.z = fmaf(v0, w.z, a0.z); a0.w = fmaf(v0, w.w, a0.w);
            a1.x = fmaf(v1, w.x, a1.x); a1.y = fmaf(v1, w.y, a1.y);
            a1.z = fmaf(v1, w.z, a1.z); a1.w = fmaf(v1, w.w, a1.w);
            if (has2) {
                float v2 = x2[i];
                a2.x = fmaf(v2, w.x, a2.x); a2.y = fmaf(v2, w.y, a2.y);
                a2.z = fmaf(v2, w.z, a2.z); a2.w = fmaf(v2, w.w, a2.w);
            }
        }
        float4 aa[3] = {a0, a1, a2};
        #pragma unroll
        for (int k = 0; k < 3; ++k) {
            int t = g * 3 + k;
            if (t < T_DIM) {
                float4 o = aa[k];
                o.x = fmaxf(o.x, 0.0f) * onrm; o.y = fmaxf(o.y, 0.0f) * onrm;
                o.z = fmaxf(o.z, 0.0f) * onrm; o.w = fmaxf(o.w, 0.0f) * onrm;
                uint2 r; r.x = pack_half2(o.x, o.y); r.y = pack_half2(o.z, o.w);
                yout[(size_t)node * 80 + t * 10 + og] = r;
            }
        }
    }
}

// Launch 4: layer 2 = pull(fp16) + matmul 40->64 relu -> fp16
__global__ __launch_bounds__(256)
void k_pullmm2(const float* __restrict__ W, const float* __restrict__ b,
               uint2* __restrict__ yout) {
    constexpr int LC = 40, NCH = 2, FIN = 40, RSF = 44, OG = 16;
    __shared__ float xsh[8][T_DIM * RSF];

    int warp = threadIdx.x >> 5, lane = threadIdx.x & 31;
    int node = blockIdx.x * 8 + warp;

    float acc[NCH][8];
    pull_node_h<LC, NCH, false>(g_hbufB, node, lane, acc);
    stage_tile<LC, NCH, FIN, RSF>(xsh[warp], lane, acc, __ldg(&g_inorm[node]));
    __syncwarp();

    // epilogue: og = lane&15, g = lane>>4 -> t = g*4+k (4 rows per lane)
    int og = lane & 15, g = lane >> 4;
    float onrm = __ldg(&g_onorm[node]);
    const float4* W4 = reinterpret_cast<const float4*>(W);
    float4 a[4];
    float4 bv = reinterpret_cast<const float4*>(b)[og];
    #pragma unroll
    for (int k = 0; k < 4; ++k) a[k] = bv;
    const float* xb = &xsh[warp][(g * 4) * RSF];
    #pragma unroll 8
    for (int i = 0; i < FIN; ++i) {
        float4 w = __ldg(&W4[i * OG + og]);
        #pragma unroll
        for (int k = 0; k < 4; ++k) {
            float v = xb[k * RSF + i];
            a[k].x = fmaf(v, w.x, a[k].x); a[k].y = fmaf(v, w.y, a[k].y);
            a[k].z = fmaf(v, w.z, a[k].z); a[k].w = fmaf(v, w.w, a[k].w);
        }
    }
    #pragma unroll
    for (int k = 0; k < 4; ++k) {
        int t = g * 4 + k;
        float4 o = a[k];
        o.x = fmaxf(o.x, 0.0f) * onrm; o.y = fmaxf(o.y, 0.0f) * onrm;
        o.z = fmaxf(o.z, 0.0f) * onrm; o.w = fmaxf(o.w, 0.0f) * onrm;
        uint2 r; r.x = pack_half2(o.x, o.y); r.y = pack_half2(o.z, o.w);
        yout[(size_t)node * 128 + t * 16 + og] = r;
    }
}

// Launch 5: layer 3 = pull(fp16) + matmul 64->64 + conv1d(k=3,pad=1) -> out fp32.
// Also self-restores the degree counters to zero for the next call.
__global__ __launch_bounds__(256)
void k_pullmm3_conv(const float* __restrict__ W, const float* __restrict__ b,
                    const float* __restrict__ bc, float* __restrict__ out) {
    constexpr int LC = 64, NCH = 2, FIN = 64, RSF = 68, RS4 = 17, OG = 16;
    __shared__ float xsh[8][576];            // [t][f] padded, reused as osh [o][t] pad-9
    __shared__ float ysh[8][T_DIM * RSF];

    int gid = blockIdx.x * blockDim.x + threadIdx.x;
    if (gid < N_NODES) { g_odeg[gid] = 0; g_indeg[gid] = 0; }

    int warp = threadIdx.x >> 5, lane = threadIdx.x & 31;
    int node = blockIdx.x * 8 + warp;

    float acc[NCH][8];
    pull_node_h<LC, NCH, false>(g_hbufA, node, lane, acc);
    stage_tile<LC, NCH, FIN, RSF>(xsh[warp], lane, acc, __ldg(&g_inorm[node]));
    __syncwarp();

    int og = lane & 15, g = lane >> 4;

    // matmul 64->64 into ysh (4 t-rows per lane, W reused 4x)
    {
        const float4* W4 = reinterpret_cast<const float4*>(W);
        float4 a[4];
        float4 bv = reinterpret_cast<const float4*>(b)[og];
        #pragma unroll
        for (int k = 0; k < 4; ++k) a[k] = bv;
        const float* xb = &xsh[warp][(g * 4) * RSF];
        #pragma unroll 8
        for (int i = 0; i < FIN; ++i) {
            float4 w = __ldg(&W4[i * OG + og]);
            #pragma unroll
            for (int k = 0; k < 4; ++k) {
                float v = xb[k * RSF + i];
                a[k].x = fmaf(v, w.x, a[k].x); a[k].y = fmaf(v, w.y, a[k].y);
                a[k].z = fmaf(v, w.z, a[k].z); a[k].w = fmaf(v, w.w, a[k].w);
            }
        }
        float4* ys4 = reinterpret_cast<float4*>(ysh[warp]);
        #pragma unroll
        for (int k = 0; k < 4; ++k)
            ys4[(g * 4 + k) * RS4 + og] = a[k];
    }
    __syncwarp();   // xsh consumed, ysh complete

    // conv over t (k=3, pad=1): lane owns og, 4 t-rows; W reused 4x per load
    float* osh = xsh[warp];
    {
        const float4* Wt4 = reinterpret_cast<const float4*>(g_WcT);
        float4 a[4];
        float4 bv = reinterpret_cast<const float4*>(bc)[og];
        #pragma unroll
        for (int k = 0; k < 4; ++k) a[k] = bv;
        #pragma unroll
        for (int kc = 0; kc < 3; ++kc) {
            #pragma unroll 8
            for (int i = 0; i < 64; ++i) {
                float4 w = __ldg(&Wt4[(kc * 64 + i) * OG + og]);
                #pragma unroll
                for (int k = 0; k < 4; ++k) {
                    int tr = g * 4 + k + kc - 1;
                    if (tr >= 0 && tr < T_DIM) {
                        float v = ysh[warp][tr * RSF + i];
                        a[k].x = fmaf(v, w.x, a[k].x); a[k].y = fmaf(v, w.y, a[k].y);
                        a[k].z = fmaf(v, w.z, a[k].z); a[k].w = fmaf(v, w.w, a[k].w);
                    }
                }
            }
        }
        int o0 = og * 4;
        #pragma unroll
        for (int k = 0; k < 4; ++k) {
            int t = g * 4 + k;
            osh[(o0 + 0) * 9 + t] = a[k].x;
            osh[(o0 + 1) * 9 + t] = a[k].y;
            osh[(o0 + 2) * 9 + t] = a[k].z;
            osh[(o0 + 3) * 9 + t] = a[k].w;
        }
    }
    __syncwarp();

    float* ob = out + (size_t)node * 512;
    #pragma unroll
    for (int k = 0; k < 16; ++k) {
        int j = lane + k * 32;
        ob[j] = osh[(j >> 3) * 9 + (j & 7)];
    }
}

// ---------------------------------------------------------------------------
extern "C" void kernel_launch(void* const* d_in, const int* in_sizes, int n_in,
                              void* d_out, int out_size) {
    const float* tf  = (const float*)d_in[0];
    const int*   src = (const int*)  d_in[1];
    const int*   dst = (const int*)  d_in[2];
    const float* W1  = (const float*)d_in[3];
    const float* b1  = (const float*)d_in[4];
    const float* W2  = (const float*)d_in[5];
    const float* b2  = (const float*)d_in[6];
    const float* W3  = (const float*)d_in[7];
    const float* b3  = (const float*)d_in[8];
    const float* Wc  = (const float*)d_in[9];
    const float* bc  = (const float*)d_in[10];
    float* out = (float*)d_out;

    uint2 *hbufB, *hbufA;
    cudaGetSymbolAddress((void**)&hbufB, g_hbufB);
    cudaGetSymbolAddress((void**)&hbufA, g_hbufA);

    const int TB = 256;

    k_degprep<<<N_NODES / 8, TB>>>(tf, src, dst);        // 0 (edges in blocks<3125)
    k_scanall<<<1, 1024>>>(Wc);                          // 1
    k_fill   <<<cdiv(N_EDGES, TB), TB>>>(src, dst);      // 2

    k_pullmm1<<<N_NODES / 8, TB>>>(W1, b1, hbufB);       // 3 (PROFILED)
    k_pullmm2<<<N_NODES / 8, TB>>>(W2, b2, hbufA);       // 4
    k_pullmm3_conv<<<N_NODES / 8, TB>>>(W3, b3, bc, out);// 5
}

// round 11
// speedup vs baseline: 2.0742x; 1.0067x over previous
#include <cuda_runtime.h>
#include <cuda_fp16.h>
#include <cstdint>

#define N_NODES 50000
#define N_EDGES 800000
#define T_DIM   8
#define NF_IN   32
#define NH1     40
#define NH2     64
#define NF_OUT  64

// Scratch (device globals; allocation-free per harness rules)
__device__ __align__(16) __half g_thf  [N_NODES * 256];   // tf transposed [n][t][32], fp16
__device__ __align__(16) __half g_hbufB[N_NODES * 320];   // layer1 out [n][t][40], fp16
__device__ __align__(16) __half g_hbufA[N_NODES * 512];   // layer2 out [n][t][64], fp16
__device__ float g_onorm[N_NODES];
__device__ float g_inorm[N_NODES];
__device__ int   g_odeg [N_NODES];   // zero on entry (static init + self-restore)
__device__ int   g_indeg[N_NODES];   // zero on entry (static init + self-restore)
__device__ int   g_offsets[N_NODES + 1];
__device__ int   g_cursor [N_NODES];
__device__ int   g_esrc [N_EDGES];
__device__ __align__(16) float g_WcT[3 * 64 * 64];        // [k][i][o]

static inline int cdiv(int a, int b) { return (a + b - 1) / b; }

__device__ __forceinline__ unsigned int pack_half2(float a, float b) {
    __half2 h = __floats2half2_rn(a, b);
    return *reinterpret_cast<unsigned int*>(&h);
}

// ---- packed f32x2 helpers (Blackwell FFMA2: 2 fp32 FMA per instruction) ----
__device__ __forceinline__ unsigned long long f2pack(float lo, float hi) {
    unsigned long long r;
    asm("mov.b64 %0, {%1, %2};" : "=l"(r) : "f"(lo), "f"(hi));
    return r;
}
__device__ __forceinline__ void f2unpack(unsigned long long v, float& lo, float& hi) {
    asm("mov.b64 {%0, %1}, %2;" : "=f"(lo), "=f"(hi) : "l"(v));
}
__device__ __forceinline__ void ffma2(unsigned long long& d,
                                      unsigned long long a, unsigned long long b) {
    asm("fma.rn.f32x2 %0, %1, %2, %3;" : "=l"(d) : "l"(a), "l"(b), "l"(d));
}

// ---------------------------------------------------------------------------
// Launch 0: degree histogram (blocks 0..3124) + tf transpose->fp16 (all blocks)
__global__ void k_degprep(const float* __restrict__ tf,
                          const int* __restrict__ src, const int* __restrict__ dst) {
    __shared__ float sh[8][32 * 9];     // per-warp node tile, padded [f][t]
    int gid = blockIdx.x * blockDim.x + threadIdx.x;
    if (gid < N_EDGES) {                // 3125*256 = 800000 exactly
        atomicAdd(&g_odeg[src[gid]], 1);
        atomicAdd(&g_indeg[dst[gid]], 1);
    }

    int w = threadIdx.x >> 5, lane = threadIdx.x & 31;
    int node = blockIdx.x * 8 + w;      // 6250*8 = 50000 exactly
    const float4* src4 = reinterpret_cast<const float4*>(tf + (size_t)node * 256);
    #pragma unroll
    for (int h = 0; h < 2; ++h) {
        float4 v = __ldg(&src4[h * 32 + lane]);
        int l = (h * 32 + lane) * 4;    // linear [f][t] index
        int f = l >> 3, t = l & 7;
        float* p = &sh[w][f * 9 + t];
        p[0] = v.x; p[1] = v.y; p[2] = v.z; p[3] = v.w;
    }
    __syncwarp();
    // write [t][f] as half: lane -> t = lane>>2, f0 = (lane&3)*8 (8 features)
    int t = lane >> 2, f0 = (lane & 3) * 8;
    float v[8];
    #pragma unroll
    for (int m = 0; m < 8; ++m) v[m] = sh[w][(f0 + m) * 9 + t];
    uint4 u;
    u.x = pack_half2(v[0], v[1]); u.y = pack_half2(v[2], v[3]);
    u.z = pack_half2(v[4], v[5]); u.w = pack_half2(v[6], v[7]);
    *reinterpret_cast<uint4*>(g_thf + (size_t)node * 256 + t * 32 + f0) = u;
}

// Launch 1: single-block fused CSR prologue (proven round-8 code)
__global__ void k_scanall(const float* __restrict__ Wc) {
    __shared__ int wsum[32];
    __shared__ int s_carry;
    int lane = threadIdx.x & 31, wid = threadIdx.x >> 5;

    for (int j = threadIdx.x; j < 3 * 64 * 64; j += 1024) {
        int k = j / 4096, rem = j % 4096;
        int ii = rem / 64, o = rem % 64;
        g_WcT[j] = Wc[(o * 64 + ii) * 3 + k];
    }
    if (threadIdx.x == 0) s_carry = 0;
    __syncthreads();

    for (int base = 0; base < N_NODES; base += 1024) {
        int idx = base + threadIdx.x;
        int v = (idx < N_NODES) ? g_indeg[idx] : 0;
        int x = v;
        #pragma unroll
        for (int o = 1; o < 32; o <<= 1) {
            int y = __shfl_up_sync(0xffffffffu, x, o);
            if (lane >= o) x += y;
        }
        if (lane == 31) wsum[wid] = x;
        __syncthreads();
        if (wid == 0) {
            int s = wsum[lane];
            #pragma unroll
            for (int o = 1; o < 32; o <<= 1) {
                int y = __shfl_up_sync(0xffffffffu, s, o);
                if (lane >= o) s += y;
            }
            wsum[lane] = s;
        }
        __syncthreads();
        int carry = s_carry;
        int wbase = (wid > 0) ? wsum[wid - 1] : 0;
        int excl = carry + wbase + x - v;
        if (idx < N_NODES) {
            g_offsets[idx] = excl;
            g_cursor[idx]  = excl;
            g_onorm[idx] = rsqrtf(fmaxf((float)g_odeg[idx], 1.0f));
            g_inorm[idx] = rsqrtf(fmaxf((float)v, 1.0f));
        }
        __syncthreads();
        if (threadIdx.x == 1023) s_carry = carry + wbase + x;
        __syncthreads();
    }
    if (threadIdx.x == 0) g_offsets[N_NODES] = s_carry;
}

// Launch 2: fill CSR edge-source list (dst-bucketed)
__global__ void k_fill(const int* __restrict__ src, const int* __restrict__ dst) {
    int i = blockIdx.x * blockDim.x + threadIdx.x;
    if (i < N_EDGES) {
        int pos = atomicAdd(&g_cursor[dst[i]], 1);
        g_esrc[pos] = src[i];
    }
}

// ---------------------------------------------------------------------------
// fp16 pull: accumulate 8 halves (one 16B chunk) into fp32 acc
template<bool SC>
__device__ __forceinline__ void acc8(const uint4 u, float s, float* a) {
    float2 f0 = __half22float2(*reinterpret_cast<const __half2*>(&u.x));
    float2 f1 = __half22float2(*reinterpret_cast<const __half2*>(&u.y));
    float2 f2 = __half22float2(*reinterpret_cast<const __half2*>(&u.z));
    float2 f3 = __half22float2(*reinterpret_cast<const __half2*>(&u.w));
    if (SC) {
        a[0] = fmaf(f0.x, s, a[0]); a[1] = fmaf(f0.y, s, a[1]);
        a[2] = fmaf(f1.x, s, a[2]); a[3] = fmaf(f1.y, s, a[3]);
        a[4] = fmaf(f2.x, s, a[4]); a[5] = fmaf(f2.y, s, a[5]);
        a[6] = fmaf(f3.x, s, a[6]); a[7] = fmaf(f3.y, s, a[7]);
    } else {
        a[0] += f0.x; a[1] += f0.y; a[2] += f1.x; a[3] += f1.y;
        a[4] += f2.x; a[5] += f2.y; a[6] += f3.x; a[7] += f3.y;
    }
}

// Pull (proven structure, fp16 rows): LC = number of 16B chunks per node row.
template<int LC, int NCH, bool SRCSCALE>
__device__ __forceinline__ void pull_node_h(const __half* __restrict__ hin,
                                            int w, int lane, float acc[][8]) {
    int beg = __ldg(&g_offsets[w]);
    int end = __ldg(&g_offsets[w + 1]);
    #pragma unroll
    for (int j = 0; j < NCH; ++j)
        #pragma unroll
        for (int m = 0; m < 8; ++m) acc[j][m] = 0.0f;

    int e = beg;
    for (; e + 2 <= end; e += 2) {
        int s0 = __ldg(&g_esrc[e]);
        int s1 = __ldg(&g_esrc[e + 1]);
        float c0 = SRCSCALE ? __ldg(&g_onorm[s0]) : 1.0f;
        float c1 = SRCSCALE ? __ldg(&g_onorm[s1]) : 1.0f;
        const uint4* h0 = reinterpret_cast<const uint4*>(hin + (size_t)s0 * (LC * 8));
        const uint4* h1 = reinterpret_cast<const uint4*>(hin + (size_t)s1 * (LC * 8));
        #pragma unroll
        for (int j = 0; j < NCH; ++j) {
            int c = lane + j * 32;
            if (c < LC) {
                uint4 a = __ldg(&h0[c]);
                uint4 b = __ldg(&h1[c]);
                acc8<SRCSCALE>(a, c0, acc[j]);
                acc8<SRCSCALE>(b, c1, acc[j]);
            }
        }
    }
    if (e < end) {
        int s0 = __ldg(&g_esrc[e]);
        float c0 = SRCSCALE ? __ldg(&g_onorm[s0]) : 1.0f;
        const uint4* h0 = reinterpret_cast<const uint4*>(hin + (size_t)s0 * (LC * 8));
        #pragma unroll
        for (int j = 0; j < NCH; ++j) {
            int c = lane + j * 32;
            if (c < LC) {
                uint4 a = __ldg(&h0[c]);
                acc8<SRCSCALE>(a, c0, acc[j]);
            }
        }
    }
}

// Stage fp32 tile into padded smem: chunk c -> t = (c*8)/FIN, f0 = (c*8)%FIN
template<int LC, int NCH, int FIN, int RSF>
__device__ __forceinline__ void stage_tile(float* __restrict__ xrow, int lane,
                                           float acc[][8], float inrm) {
    constexpr int CPT = FIN / 8;   // chunks per t-row
    #pragma unroll
    for (int j = 0; j < NCH; ++j) {
        int c = lane + j * 32;
        if (c < LC) {
            int t = c / CPT, f0 = (c % CPT) * 8;
            float* p = xrow + t * RSF + f0;
            float4 v0 = make_float4(acc[j][0] * inrm, acc[j][1] * inrm,
                                    acc[j][2] * inrm, acc[j][3] * inrm);
            float4 v1 = make_float4(acc[j][4] * inrm, acc[j][5] * inrm,
                                    acc[j][6] * inrm, acc[j][7] * inrm);
            *reinterpret_cast<float4*>(p)     = v0;
            *reinterpret_cast<float4*>(p + 4) = v1;
        }
    }
}

// ---------------------------------------------------------------------------
// Launch 3 (PROFILED): layer 1 = pull(tf fp16) + matmul 32->40 relu -> fp16
__global__ __launch_bounds__(256)
void k_pullmm1(const float* __restrict__ W, const float* __restrict__ b,
               uint2* __restrict__ yout) {
    constexpr int LC = 32, NCH = 1, FIN = 32, RSF = 36, OG = 10;
    __shared__ float xsh[8][T_DIM * RSF];

    int warp = threadIdx.x >> 5, lane = threadIdx.x & 31;
    int node = blockIdx.x * 8 + warp;

    float acc[NCH][8];
    pull_node_h<LC, NCH, true>(g_thf, node, lane, acc);
    stage_tile<LC, NCH, FIN, RSF>(xsh[warp], lane, acc, __ldg(&g_inorm[node]));
    __syncwarp();

    // epilogue (FFMA2): lane -> og = lane%10, g = lane/10 (3 t-rows each)
    if (lane < 30) {
        int og = lane % OG, g = lane / OG;
        float onrm = __ldg(&g_onorm[node]);
        const ulonglong2* W2p = reinterpret_cast<const ulonglong2*>(W);
        float4 bv = reinterpret_cast<const float4*>(b)[og];
        unsigned long long bxy = f2pack(bv.x, bv.y), bzw = f2pack(bv.z, bv.w);
        unsigned long long a0xy = bxy, a0zw = bzw;
        unsigned long long a1xy = bxy, a1zw = bzw;
        unsigned long long a2xy = bxy, a2zw = bzw;
        const float* x0 = &xsh[warp][(g * 3 + 0) * RSF];
        const float* x1 = &xsh[warp][(g * 3 + 1) * RSF];
        const float* x2 = &xsh[warp][(g * 3 + 2) * RSF];   // t=8 slot unused if g==2
        bool has2 = (g * 3 + 2) < T_DIM;
        #pragma unroll 8
        for (int i = 0; i < FIN; ++i) {
            ulonglong2 ww = __ldg(&W2p[i * OG + og]);
            unsigned long long v0 = f2pack(x0[i], x0[i]);
            unsigned long long v1 = f2pack(x1[i], x1[i]);
            ffma2(a0xy, v0, ww.x); ffma2(a0zw, v0, ww.y);
            ffma2(a1xy, v1, ww.x); ffma2(a1zw, v1, ww.y);
            if (has2) {
                unsigned long long v2 = f2pack(x2[i], x2[i]);
                ffma2(a2xy, v2, ww.x); ffma2(a2zw, v2, ww.y);
            }
        }
        unsigned long long axy[3] = {a0xy, a1xy, a2xy};
        unsigned long long azw[3] = {a0zw, a1zw, a2zw};
        #pragma unroll
        for (int k = 0; k < 3; ++k) {
            int t = g * 3 + k;
            if (t < T_DIM) {
                float ox, oy, oz, ow;
                f2unpack(axy[k], ox, oy);
                f2unpack(azw[k], oz, ow);
                ox = fmaxf(ox, 0.0f) * onrm; oy = fmaxf(oy, 0.0f) * onrm;
                oz = fmaxf(oz, 0.0f) * onrm; ow = fmaxf(ow, 0.0f) * onrm;
                uint2 r; r.x = pack_half2(ox, oy); r.y = pack_half2(oz, ow);
                yout[(size_t)node * 80 + t * 10 + og] = r;
            }
        }
    }
}

// Launch 4: layer 2 = pull(fp16) + matmul 40->64 relu -> fp16
__global__ __launch_bounds__(256)
void k_pullmm2(const float* __restrict__ W, const float* __restrict__ b,
               uint2* __restrict__ yout) {
    constexpr int LC = 40, NCH = 2, FIN = 40, RSF = 44, OG = 16;
    __shared__ float xsh[8][T_DIM * RSF];

    int warp = threadIdx.x >> 5, lane = threadIdx.x & 31;
    int node = blockIdx.x * 8 + warp;

    float acc[NCH][8];
    pull_node_h<LC, NCH, false>(g_hbufB, node, lane, acc);
    stage_tile<LC, NCH, FIN, RSF>(xsh[warp], lane, acc, __ldg(&g_inorm[node]));
    __syncwarp();

    // epilogue (FFMA2): og = lane&15, g = lane>>4 -> 4 t-rows per lane
    int og = lane & 15, g = lane >> 4;
    float onrm = __ldg(&g_onorm[node]);
    const ulonglong2* W2p = reinterpret_cast<const ulonglong2*>(W);
    float4 bv = reinterpret_cast<const float4*>(b)[og];
    unsigned long long axy[4], azw[4];
    {
        unsigned long long bxy = f2pack(bv.x, bv.y), bzw = f2pack(bv.z, bv.w);
        #pragma unroll
        for (int k = 0; k < 4; ++k) { axy[k] = bxy; azw[k] = bzw; }
    }
    const float* xb = &xsh[warp][(g * 4) * RSF];
    #pragma unroll 8
    for (int i = 0; i < FIN; ++i) {
        ulonglong2 ww = __ldg(&W2p[i * OG + og]);
        #pragma unroll
        for (int k = 0; k < 4; ++k) {
            float v = xb[k * RSF + i];
            unsigned long long vv = f2pack(v, v);
            ffma2(axy[k], vv, ww.x);
            ffma2(azw[k], vv, ww.y);
        }
    }
    #pragma unroll
    for (int k = 0; k < 4; ++k) {
        int t = g * 4 + k;
        float ox, oy, oz, ow;
        f2unpack(axy[k], ox, oy);
        f2unpack(azw[k], oz, ow);
        ox = fmaxf(ox, 0.0f) * onrm; oy = fmaxf(oy, 0.0f) * onrm;
        oz = fmaxf(oz, 0.0f) * onrm; ow = fmaxf(ow, 0.0f) * onrm;
        uint2 r; r.x = pack_half2(ox, oy); r.y = pack_half2(oz, ow);
        yout[(size_t)node * 128 + t * 16 + og] = r;
    }
}

// Launch 5: layer 3 = pull(fp16) + matmul 64->64 + conv1d(k=3,pad=1) -> out fp32.
// Also self-restores the degree counters to zero for the next call.
__global__ __launch_bounds__(256)
void k_pullmm3_conv(const float* __restrict__ W, const float* __restrict__ b,
                    const float* __restrict__ bc, float* __restrict__ out) {
    constexpr int LC = 64, NCH = 2, FIN = 64, RSF = 68, RS4 = 17, OG = 16;
    __shared__ float xsh[8][576];            // [t][f] padded, reused as osh [o][t] pad-9
    __shared__ float ysh[8][T_DIM * RSF];

    int gid = blockIdx.x * blockDim.x + threadIdx.x;
    if (gid < N_NODES) { g_odeg[gid] = 0; g_indeg[gid] = 0; }

    int warp = threadIdx.x >> 5, lane = threadIdx.x & 31;
    int node = blockIdx.x * 8 + warp;

    float acc[NCH][8];
    pull_node_h<LC, NCH, false>(g_hbufA, node, lane, acc);
    stage_tile<LC, NCH, FIN, RSF>(xsh[warp], lane, acc, __ldg(&g_inorm[node]));
    __syncwarp();

    int og = lane & 15, g = lane >> 4;

    // matmul 64->64 into ysh (FFMA2, 4 t-rows per lane, W reused 4x)
    {
        const ulonglong2* W2p = reinterpret_cast<const ulonglong2*>(W);
        float4 bv = reinterpret_cast<const float4*>(b)[og];
        unsigned long long axy[4], azw[4];
        unsigned long long bxy = f2pack(bv.x, bv.y), bzw = f2pack(bv.z, bv.w);
        #pragma unroll
        for (int k = 0; k < 4; ++k) { axy[k] = bxy; azw[k] = bzw; }
        const float* xb = &xsh[warp][(g * 4) * RSF];
        #pragma unroll 8
        for (int i = 0; i < FIN; ++i) {
            ulonglong2 ww = __ldg(&W2p[i * OG + og]);
            #pragma unroll
            for (int k = 0; k < 4; ++k) {
                float v = xb[k * RSF + i];
                unsigned long long vv = f2pack(v, v);
                ffma2(axy[k], vv, ww.x);
                ffma2(azw[k], vv, ww.y);
            }
        }
        float4* ys4 = reinterpret_cast<float4*>(ysh[warp]);
        #pragma unroll
        for (int k = 0; k < 4; ++k) {
            float ox, oy, oz, ow;
            f2unpack(axy[k], ox, oy);
            f2unpack(azw[k], oz, ow);
            ys4[(g * 4 + k) * RS4 + og] = make_float4(ox, oy, oz, ow);
        }
    }
    __syncwarp();   // xsh consumed, ysh complete

    // conv over t (k=3, pad=1): FFMA2; lane owns og, 4 t-rows; W reused 4x
    float* osh = xsh[warp];
    {
        const ulonglong2* Wt2 = reinterpret_cast<const ulonglong2*>(g_WcT);
        float4 bv = reinterpret_cast<const float4*>(bc)[og];
        unsigned long long axy[4], azw[4];
        unsigned long long bxy = f2pack(bv.x, bv.y), bzw = f2pack(bv.z, bv.w);
        #pragma unroll
        for (int k = 0; k < 4; ++k) { axy[k] = bxy; azw[k] = bzw; }
        #pragma unroll
        for (int kc = 0; kc < 3; ++kc) {
            #pragma unroll 8
            for (int i = 0; i < 64; ++i) {
                ulonglong2 ww = __ldg(&Wt2[(kc * 64 + i) * OG + og]);
                #pragma unroll
                for (int k = 0; k < 4; ++k) {
                    int tr = g * 4 + k + kc - 1;
                    if (tr >= 0 && tr < T_DIM) {
                        float v = ysh[warp][tr * RSF + i];
                        unsigned long long vv = f2pack(v, v);
                        ffma2(axy[k], vv, ww.x);
                        ffma2(azw[k], vv, ww.y);
                    }
                }
            }
        }
        int o0 = og * 4;
        #pragma unroll
        for (int k = 0; k < 4; ++k) {
            int t = g * 4 + k;
            float ox, oy, oz, ow;
            f2unpack(axy[k], ox, oy);
            f2unpack(azw[k], oz, ow);
            osh[(o0 + 0) * 9 + t] = ox;
            osh[(o0 + 1) * 9 + t] = oy;
            osh[(o0 + 2) * 9 + t] = oz;
            osh[(o0 + 3) * 9 + t] = ow;
        }
    }
    __syncwarp();

    float* ob = out + (size_t)node * 512;
    #pragma unroll
    for (int k = 0; k < 16; ++k) {
        int j = lane + k * 32;
        ob[j] = osh[(j >> 3) * 9 + (j & 7)];
    }
}

// ---------------------------------------------------------------------------
extern "C" void kernel_launch(void* const* d_in, const int* in_sizes, int n_in,
                              void* d_out, int out_size) {
    const float* tf  = (const float*)d_in[0];
    const int*   src = (const int*)  d_in[1];
    const int*   dst = (const int*)  d_in[2];
    const float* W1  = (const float*)d_in[3];
    const float* b1  = (const float*)d_in[4];
    const float* W2  = (const float*)d_in[5];
    const float* b2  = (const float*)d_in[6];
    const float* W3  = (const float*)d_in[7];
    const float* b3  = (const float*)d_in[8];
    const float* Wc  = (const float*)d_in[9];
    const float* bc  = (const float*)d_in[10];
    float* out = (float*)d_out;

    uint2 *hbufB, *hbufA;
    cudaGetSymbolAddress((void**)&hbufB, g_hbufB);
    cudaGetSymbolAddress((void**)&hbufA, g_hbufA);

    const int TB = 256;

    k_degprep<<<N_NODES / 8, TB>>>(tf, src, dst);        // 0 (edges in blocks<3125)
    k_scanall<<<1, 1024>>>(Wc);                          // 1
    k_fill   <<<cdiv(N_EDGES, TB), TB>>>(src, dst);      // 2

    k_pullmm1<<<N_NODES / 8, TB>>>(W1, b1, hbufB);       // 3 (PROFILED)
    k_pullmm2<<<N_NODES / 8, TB>>>(W2, b2, hbufA);       // 4
    k_pullmm3_conv<<<N_NODES / 8, TB>>>(W3, b3, bc, out);// 5
}